// round 14
// baseline (speedup 1.0000x reference)
#include <cuda_runtime.h>
#include <cuda_bf16.h>
#include <cstdint>

#define F_ 48
#define C_ 128
#define GF 192
#define THREADS 128
#define SCALE_C 0.999f

// ---- smem layout (bytes) ----
#define BFS 136   // W row stride in bf16 elems (272B -> conflict-free ldmatrix, trans and non-trans)
#define OFF_W   0                          // W[e][c] bf16, raw
#define OFF_QE  (OFF_W + GF*BFS*2)         // 52224
#define OFF_QM  (OFF_QE + 3072)            // 55296
#define OFF_ISC (OFF_QM + 3072)            // 58368
#define OFF_LSC (OFF_ISC + 192)            // 58560
#define SMEM_BYTES (OFF_LSC + 192)         // 58752

struct Precomp {
    float Qeff[F_][4][4];
    float Qm[F_][4][4];
    float its[F_];
    float invsc[2][F_];
    float lscal[2][F_];
    float eps_e;
    float inv_denom;
};
__device__ Precomp g_pre;

__device__ __forceinline__ uint32_t smem_u32(const void* p) {
    uint32_t a;
    asm("{ .reg .u64 t; cvta.to.shared.u64 t, %1; cvt.u32.u64 %0, t; }" : "=r"(a) : "l"(p));
    return a;
}
// pack: a -> low 16 bits, b -> high
__device__ __forceinline__ uint32_t packbf(float a, float b) {
    uint32_t r;
    asm("cvt.rn.bf16x2.f32 %0, %1, %2;" : "=r"(r) : "f"(b), "f"(a));
    return r;
}
__device__ __forceinline__ float2 unpackbf(uint32_t v) {
    float2 r;
    r.x = __uint_as_float(v << 16);
    r.y = __uint_as_float(v & 0xffff0000u);
    return r;
}
__device__ __forceinline__ void ldsm4(uint32_t* r, uint32_t addr) {
    asm volatile("ldmatrix.sync.aligned.m8n8.x4.shared.b16 {%0,%1,%2,%3}, [%4];"
                 : "=r"(r[0]), "=r"(r[1]), "=r"(r[2]), "=r"(r[3]) : "r"(addr));
}
__device__ __forceinline__ void ldsm4t(uint32_t* r, uint32_t addr) {
    asm volatile("ldmatrix.sync.aligned.m8n8.x4.trans.shared.b16 {%0,%1,%2,%3}, [%4];"
                 : "=r"(r[0]), "=r"(r[1]), "=r"(r[2]), "=r"(r[3]) : "r"(addr));
}
__device__ __forceinline__ void mma16816(float* d, const uint32_t* a, const uint32_t* b) {
    asm volatile(
        "mma.sync.aligned.m16n8k16.row.col.f32.bf16.bf16.f32 "
        "{%0,%1,%2,%3}, {%4,%5,%6,%7}, {%8,%9}, {%0,%1,%2,%3};"
        : "+f"(d[0]), "+f"(d[1]), "+f"(d[2]), "+f"(d[3])
        : "r"(a[0]), "r"(a[1]), "r"(a[2]), "r"(a[3]), "r"(b[0]), "r"(b[1]));
}

__device__ __forceinline__ void proj4(float x0, float x1, float x2, float x3,
                                      float& o0, float& o1, float& o2, float& o3) {
    float a0 = fabsf(x0), a1 = fabsf(x1), a2 = fabsf(x2), a3 = fabsf(x3);
    float ssum = a0 + a1 + a2 + a3;
    float m01 = fmaxf(a0, a1), n01 = fminf(a0, a1);
    float m23 = fmaxf(a2, a3), n23 = fminf(a2, a3);
    float s0 = fmaxf(m01, m23), lo0 = fminf(m01, m23);
    float hi1 = fmaxf(n01, n23), s3 = fminf(n01, n23);
    float s1 = fmaxf(lo0, hi1), s2 = fminf(lo0, hi1);
    float c1 = s0 - 1.f, c2 = c1 + s1, c3 = c2 + s2, c4 = c3 + s3;
    int rho = 1 + (s1 * 2.f > c2) + (s2 * 3.f > c3) + (s3 * 4.f > c4);
    float num = (rho == 1) ? c1 : (rho == 2) ? c2 : (rho == 3) ? c3 : c4;
    float theta = fmaxf(num / (float)rho, 0.f);
    theta = (ssum <= 1.f) ? 0.f : theta;
    o0 = copysignf(fmaxf(a0 - theta, 0.f), x0);
    o1 = copysignf(fmaxf(a1 - theta, 0.f), x1);
    o2 = copysignf(fmaxf(a2 - theta, 0.f), x2);
    o3 = copysignf(fmaxf(a3 - theta, 0.f), x3);
}

// ---------------- precompute kernel (float Jacobi, 12 sweeps) ----------------
__global__ void precomp_kernel(const float* __restrict__ sigma, const float* __restrict__ Qp,
                               const float* __restrict__ tausp, const float* __restrict__ lambp,
                               const float* __restrict__ epsp,
                               const float* __restrict__ w1, const float* __restrict__ b1,
                               const float* __restrict__ w2, const float* __restrict__ b2,
                               const float* __restrict__ w3, const float* __restrict__ b3) {
    __shared__ float h1[2][F_], h2[2][F_];
    int t = threadIdx.x;
    float lamb_e = expf(lambp[0]);
    float eps_e = expf(epsp[0]);
    if (t == 0) {
        g_pre.eps_e = eps_e;
        g_pre.inv_denom = 1.f / (1.f + lamb_e * (1.f + eps_e));
    }
    if (t < F_) {
        float Qm[4][4];
#pragma unroll
        for (int l = 0; l < 4; l++) {
            float rs = 0.f;
#pragma unroll
            for (int g = 0; g < 4; g++) rs += fabsf(Qp[t * 16 + l * 4 + g]);
            float inv = 1.f / fmaxf(rs, 1.f);
#pragma unroll
            for (int g = 0; g < 4; g++) Qm[l][g] = Qp[t * 16 + l * 4 + g] * inv;
        }
        float S[4][4];
        for (int i = 0; i < 4; i++)
            for (int j = 0; j < 4; j++) {
                float acc = 0.f;
                for (int l = 0; l < 4; l++) acc += Qm[l][i] * Qm[l][j];
                S[i][j] = acc;
            }
        const int JP[6] = {0, 0, 0, 1, 1, 2};
        const int JQ[6] = {1, 2, 3, 2, 3, 3};
        for (int sw = 0; sw < 12; sw++)
            for (int rr = 0; rr < 6; rr++) {
                int p = JP[rr], qq = JQ[rr];
                float apq = S[p][qq];
                if (fabsf(apq) < 1e-20f) continue;
                float th = (S[qq][qq] - S[p][p]) / (2.f * apq);
                float tt = (th >= 0.f ? 1.f : -1.f) / (fabsf(th) + sqrtf(1.f + th * th));
                float cc = rsqrtf(1.f + tt * tt), ss = tt * cc;
                for (int k = 0; k < 4; k++) {
                    float skp = S[k][p], skq = S[k][qq];
                    S[k][p] = cc * skp - ss * skq;
                    S[k][qq] = ss * skp + cc * skq;
                }
                for (int k = 0; k < 4; k++) {
                    float spk = S[p][k], sqk = S[qq][k];
                    S[p][k] = cc * spk - ss * sqk;
                    S[qq][k] = ss * spk + cc * sqk;
                }
            }
        float lam = S[0][0];
        for (int i = 1; i < 4; i++) lam = (S[i][i] > lam) ? S[i][i] : lam;
        float inv_lam = 1.f / lam;
#pragma unroll
        for (int l = 0; l < 4; l++)
#pragma unroll
            for (int g = 0; g < 4; g++) {
                g_pre.Qm[t][l][g] = Qm[l][g];
                g_pre.Qeff[t][l][g] = Qm[l][g] * inv_lam;
            }
        g_pre.its[t] = SCALE_C / expf(fmaxf(tausp[t], 0.f));
        for (int bb = 0; bb < 2; bb++)
            h1[bb][t] = fmaxf(fmaf(sigma[bb] * 20.f - 2.f, w1[t], b1[t]), 0.f);
    }
    __syncthreads();
    if (t < F_)
        for (int bb = 0; bb < 2; bb++) {
            float a = b2[t];
            for (int j = 0; j < F_; j++) a += h1[bb][j] * w2[j * F_ + t];
            h2[bb][t] = fmaxf(a, 0.f);
        }
    __syncthreads();
    if (t < F_)
        for (int bb = 0; bb < 2; bb++) {
            float a = b3[t];
            for (int j = 0; j < F_; j++) a += h2[bb][j] * w3[j * F_ + t];
            float sc = fmaxf(fmaf(a, 0.05f, sigma[bb]), 0.f) + 1e-9f;
            g_pre.invsc[bb][t] = 1.f / sc;
            g_pre.lscal[bb][t] = lamb_e * sc;
        }
}

// ---------------- HMMA main kernel: bounded unrolling to stop spills ----------------
__global__ void __launch_bounds__(THREADS, 2)
mfoe_kernel(const float* __restrict__ xn, const float* __restrict__ Wf,
            const int* __restrict__ niter_p, float* __restrict__ out) {
    extern __shared__ char smc[];
    const uint32_t smb = smem_u32(smc);
    const int t = threadIdx.x;
    const int warp = t >> 5, lane = t & 31;
    const int r = lane >> 2, q = lane & 3;
    const int t8 = lane & 7, tb = lane >> 3;

    const int pix0 = blockIdx.x * 64;
    const int b = pix0 >> 14;
    const int sp0 = pix0 & 16383;
    const float* xnw = xn + (size_t)b * (C_ * 16384) + sp0 + warp * 16 + r;
    float* outw = out + (size_t)b * (C_ * 16384) + sp0 + warp * 16 + r;

    // ---- fill shared W tile (raw bf16) + Q tables + per-f scalars ----
    {
        __nv_bfloat16* wt = (__nv_bfloat16*)(smc + OFF_W);
        for (int i = t; i < GF * C_; i += THREADS) {
            int e = i >> 7, c = i & 127;
            wt[e * BFS + c] = __float2bfloat16(Wf[i]);
        }
        float* qes = (float*)(smc + OFF_QE);
        float* qms = (float*)(smc + OFF_QM);
        for (int i = t; i < 768; i += THREADS) {
            qes[i] = ((const float*)g_pre.Qeff)[i] * g_pre.its[i >> 4];
            qms[i] = ((const float*)g_pre.Qm)[i] * SCALE_C;
        }
        if (t < F_) {
            ((float*)(smc + OFF_ISC))[t] = g_pre.invsc[b][t];
            ((float*)(smc + OFF_LSC))[t] = g_pre.lscal[b][t];
        }
    }
    __syncthreads();

    const float eps_e = g_pre.eps_e;
    const float inv_denom = g_pre.inv_denom;
    const int niter = *niter_p;
    const float* qes = (const float*)(smc + OFF_QE);
    const float* qms = (const float*)(smc + OFF_QM);
    const float* ISC = (const float*)(smc + OFF_ISC);
    const float* LSC = (const float*)(smc + OFF_LSC);

    // ---- x state as packed bf16 hi/lo A-fragments ----
    uint32_t Ahs[8][4], Als[8][4];
#pragma unroll
    for (int n = 0; n < 16; n++) {
        int c0 = 8 * n + 2 * q;
        float x0 = xnw[(size_t)c0 * 16384];
        float x1 = xnw[(size_t)(c0 + 1) * 16384];
        float x2 = xnw[(size_t)c0 * 16384 + 8];
        float x3 = xnw[(size_t)(c0 + 1) * 16384 + 8];
        int m = n >> 1, base = (n & 1) * 2;
        Ahs[m][base] = packbf(x0, x1);
        float2 h0 = unpackbf(Ahs[m][base]);
        Als[m][base] = packbf(x0 - h0.x, x1 - h0.y);
        Ahs[m][base + 1] = packbf(x2, x3);
        float2 h1 = unpackbf(Ahs[m][base + 1]);
        Als[m][base + 1] = packbf(x2 - h1.x, x3 - h1.y);
    }

    for (int it = 0; it < niter; ++it) {
        uint32_t vh[24][2];   // v tiles, packed bf16

        // ===== forward (2-term: exact x, bf16 W) + activation =====
#pragma unroll
        for (int r6 = 0; r6 < 6; r6++) {
            float Df[4][4];
#pragma unroll
            for (int g = 0; g < 4; g++) { Df[g][0] = 0.f; Df[g][1] = 0.f; Df[g][2] = 0.f; Df[g][3] = 0.f; }
#pragma unroll 1
            for (int jp = 0; jp < 4; jp++) {
                uint32_t rowoff = smb + OFF_W + (uint32_t)(t8 * BFS + 32 * jp + 8 * tb) * 2;
#pragma unroll
                for (int g = 0; g < 4; g++) {
                    int n = r6 + 6 * g;
                    uint32_t bh[4];
                    ldsm4(bh, rowoff + (uint32_t)(8 * n * BFS) * 2);
                    mma16816(Df[g], Ahs[2 * jp], bh);
                    mma16816(Df[g], Als[2 * jp], bh);
                    mma16816(Df[g], Ahs[2 * jp + 1], bh + 2);
                    mma16816(Df[g], Als[2 * jp + 1], bh + 2);
                }
            }

            // activation on the quad -> vh[e-tile = r6 + 6g]; Q tables streamed
            {
                float vt[2][2][4];   // [h][fcol][g]
#pragma unroll
                for (int fcol = 0; fcol < 2; fcol++) {
                    int f = 8 * r6 + 2 * q + fcol;
                    float isc = ISC[f];
                    float ls  = LSC[f];
#pragma unroll
                    for (int h = 0; h < 2; h++) {
                        int di = 2 * h + fcol;
                        float xv0 = Df[0][di] * isc, xv1 = Df[1][di] * isc;
                        float xv2 = Df[2][di] * isc, xv3 = Df[3][di] * isc;

                        float gc0, gc1, gc2, gc3;
                        proj4(xv0, xv1, xv2, xv3, gc0, gc1, gc2, gc3);
                        gc0 = fmaf(eps_e, xv0, gc0);
                        gc1 = fmaf(eps_e, xv1, gc1);
                        gc2 = fmaf(eps_e, xv2, gc2);
                        gc3 = fmaf(eps_e, xv3, gc3);

                        float y[4];
#pragma unroll
                        for (int l = 0; l < 4; l++) {
                            float4 qe = *(const float4*)(qes + f * 16 + 4 * l);
                            y[l] = qe.x * xv0 + qe.y * xv1 + qe.z * xv2 + qe.w * xv3;
                        }

                        float gy[4];
                        proj4(y[0], y[1], y[2], y[3], gy[0], gy[1], gy[2], gy[3]);
#pragma unroll
                        for (int l = 0; l < 4; l++) gy[l] = fmaf(eps_e, y[l], gy[l]);

                        float v0 = gc0, v1 = gc1, v2 = gc2, v3 = gc3;
#pragma unroll
                        for (int l = 0; l < 4; l++) {
                            float4 qm = *(const float4*)(qms + f * 16 + 4 * l);
                            v0 -= qm.x * gy[l];
                            v1 -= qm.y * gy[l];
                            v2 -= qm.z * gy[l];
                            v3 -= qm.w * gy[l];
                        }
                        vt[h][fcol][0] = ls * v0;
                        vt[h][fcol][1] = ls * v1;
                        vt[h][fcol][2] = ls * v2;
                        vt[h][fcol][3] = ls * v3;
                    }
                }
#pragma unroll
                for (int g = 0; g < 4; g++) {
                    vh[r6 + 6 * g][0] = packbf(vt[0][0][g], vt[0][1][g]);
                    vh[r6 + 6 * g][1] = packbf(vt[1][0][g], vt[1][1][g]);
                }
            }
        }

        // ===== backward (1-term, trans-ldsm from the SAME W tile) + x update =====
#pragma unroll
        for (int p = 0; p < 8; p++) {
            float acc0[4] = {0.f, 0.f, 0.f, 0.f};
            float acc1[4] = {0.f, 0.f, 0.f, 0.f};
            uint32_t coloff = (uint32_t)(16 * p + 8 * (tb >> 1)) * 2;
            uint32_t rowb = (uint32_t)(t8 + 8 * (tb & 1));
#pragma unroll 2
            for (int jp = 0; jp < 12; jp++) {
                uint32_t bt[4];
                ldsm4t(bt, smb + OFF_W + (uint32_t)((16 * jp + rowb) * BFS) * 2 + coloff);
                uint32_t A[4] = {vh[2 * jp][0], vh[2 * jp][1], vh[2 * jp + 1][0], vh[2 * jp + 1][1]};
                mma16816(acc0, A, bt);
                mma16816(acc1, A, bt + 2);
            }
#pragma unroll
            for (int s = 0; s < 2; s++) {
                const float* ac = s ? acc1 : acc0;
                int n = 2 * p + s;
                int c0 = 8 * n + 2 * q;
                float n0 = xnw[(size_t)c0 * 16384];
                float n1 = xnw[(size_t)(c0 + 1) * 16384];
                float n2 = xnw[(size_t)c0 * 16384 + 8];
                float n3 = xnw[(size_t)(c0 + 1) * 16384 + 8];
                int m = p, base = s * 2;
                float2 h0 = unpackbf(Ahs[m][base]);
                float2 h1 = unpackbf(Ahs[m][base + 1]);
                float2 l0 = unpackbf(Als[m][base]);
                float2 l1 = unpackbf(Als[m][base + 1]);
                float x0 = h0.x + l0.x, x1 = h0.y + l0.y;
                float x2 = h1.x + l1.x, x3 = h1.y + l1.y;
                x0 -= (x0 - n0 + ac[0]) * inv_denom;
                x1 -= (x1 - n1 + ac[1]) * inv_denom;
                x2 -= (x2 - n2 + ac[2]) * inv_denom;
                x3 -= (x3 - n3 + ac[3]) * inv_denom;
                Ahs[m][base] = packbf(x0, x1);
                float2 nh0 = unpackbf(Ahs[m][base]);
                Als[m][base] = packbf(x0 - nh0.x, x1 - nh0.y);
                Ahs[m][base + 1] = packbf(x2, x3);
                float2 nh1 = unpackbf(Ahs[m][base + 1]);
                Als[m][base + 1] = packbf(x2 - nh1.x, x3 - nh1.y);
            }
        }
    }

    // ---- output: reconstruct and store ----
#pragma unroll
    for (int n = 0; n < 16; n++) {
        int c0 = 8 * n + 2 * q;
        int m = n >> 1, base = (n & 1) * 2;
        float2 h0 = unpackbf(Ahs[m][base]);
        float2 h1 = unpackbf(Ahs[m][base + 1]);
        float2 l0 = unpackbf(Als[m][base]);
        float2 l1 = unpackbf(Als[m][base + 1]);
        outw[(size_t)c0 * 16384] = h0.x + l0.x;
        outw[(size_t)(c0 + 1) * 16384] = h0.y + l0.y;
        outw[(size_t)c0 * 16384 + 8] = h1.x + l1.x;
        outw[(size_t)(c0 + 1) * 16384 + 8] = h1.y + l1.y;
    }
}

extern "C" void kernel_launch(void* const* d_in, const int* in_sizes, int n_in,
                              void* d_out, int out_size) {
    const float* xn    = (const float*)d_in[0];
    const float* sigma = (const float*)d_in[1];
    const float* Qp    = (const float*)d_in[2];
    const float* tausp = (const float*)d_in[3];
    const float* lamb  = (const float*)d_in[4];
    const float* epso  = (const float*)d_in[5];
    const float* w1    = (const float*)d_in[6];
    const float* b1    = (const float*)d_in[7];
    const float* w2    = (const float*)d_in[8];
    const float* b2    = (const float*)d_in[9];
    const float* w3    = (const float*)d_in[10];
    const float* b3    = (const float*)d_in[11];
    const float* Wf    = (const float*)d_in[12];
    const int* niter   = (const int*)d_in[13];
    float* out = (float*)d_out;

    cudaFuncSetAttribute(mfoe_kernel, cudaFuncAttributeMaxDynamicSharedMemorySize, SMEM_BYTES);
    precomp_kernel<<<1, 64>>>(sigma, Qp, tausp, lamb, epso, w1, b1, w2, b2, w3, b3);
    mfoe_kernel<<<512, THREADS, SMEM_BYTES>>>(xn, Wf, niter, out);
}

// round 15
// speedup vs baseline: 1.2095x; 1.2095x over previous
#include <cuda_runtime.h>
#include <cuda_bf16.h>
#include <cstdint>

#define F_ 48
#define C_ 128
#define GF 192
#define THREADS 128
#define SCALE_C 0.999f

// ---- smem layout (bytes) ----
#define BFS 136   // W row stride in bf16 elems (272B -> conflict-free ldmatrix, trans and non-trans)
#define OFF_W   0                          // W[e][c] bf16, raw
#define OFF_QE  (OFF_W + GF*BFS*2)         // 52224
#define OFF_QM  (OFF_QE + 3072)            // 55296
#define OFF_ISC (OFF_QM + 3072)            // 58368
#define OFF_LSC (OFF_ISC + 192)            // 58560
#define SMEM_BYTES (OFF_LSC + 192)         // 58752

struct Precomp {
    float Qeff[F_][4][4];
    float Qm[F_][4][4];
    float its[F_];
    float invsc[2][F_];
    float lscal[2][F_];
    float eps_e;
    float inv_denom;
};
__device__ Precomp g_pre;

__device__ __forceinline__ uint32_t smem_u32(const void* p) {
    uint32_t a;
    asm("{ .reg .u64 t; cvta.to.shared.u64 t, %1; cvt.u32.u64 %0, t; }" : "=r"(a) : "l"(p));
    return a;
}
// pack: a -> low 16 bits, b -> high
__device__ __forceinline__ uint32_t packbf(float a, float b) {
    uint32_t r;
    asm("cvt.rn.bf16x2.f32 %0, %1, %2;" : "=r"(r) : "f"(b), "f"(a));
    return r;
}
__device__ __forceinline__ float2 unpackbf(uint32_t v) {
    float2 r;
    r.x = __uint_as_float(v << 16);
    r.y = __uint_as_float(v & 0xffff0000u);
    return r;
}
__device__ __forceinline__ void ldsm4(uint32_t* r, uint32_t addr) {
    asm volatile("ldmatrix.sync.aligned.m8n8.x4.shared.b16 {%0,%1,%2,%3}, [%4];"
                 : "=r"(r[0]), "=r"(r[1]), "=r"(r[2]), "=r"(r[3]) : "r"(addr));
}
__device__ __forceinline__ void ldsm4t(uint32_t* r, uint32_t addr) {
    asm volatile("ldmatrix.sync.aligned.m8n8.x4.trans.shared.b16 {%0,%1,%2,%3}, [%4];"
                 : "=r"(r[0]), "=r"(r[1]), "=r"(r[2]), "=r"(r[3]) : "r"(addr));
}
__device__ __forceinline__ void mma16816(float* d, const uint32_t* a, const uint32_t* b) {
    asm volatile(
        "mma.sync.aligned.m16n8k16.row.col.f32.bf16.bf16.f32 "
        "{%0,%1,%2,%3}, {%4,%5,%6,%7}, {%8,%9}, {%0,%1,%2,%3};"
        : "+f"(d[0]), "+f"(d[1]), "+f"(d[2]), "+f"(d[3])
        : "r"(a[0]), "r"(a[1]), "r"(a[2]), "r"(a[3]), "r"(b[0]), "r"(b[1]));
}

__device__ __forceinline__ void proj4(float x0, float x1, float x2, float x3,
                                      float& o0, float& o1, float& o2, float& o3) {
    float a0 = fabsf(x0), a1 = fabsf(x1), a2 = fabsf(x2), a3 = fabsf(x3);
    float ssum = a0 + a1 + a2 + a3;
    float m01 = fmaxf(a0, a1), n01 = fminf(a0, a1);
    float m23 = fmaxf(a2, a3), n23 = fminf(a2, a3);
    float s0 = fmaxf(m01, m23), lo0 = fminf(m01, m23);
    float hi1 = fmaxf(n01, n23), s3 = fminf(n01, n23);
    float s1 = fmaxf(lo0, hi1), s2 = fminf(lo0, hi1);
    float c1 = s0 - 1.f, c2 = c1 + s1, c3 = c2 + s2, c4 = c3 + s3;
    int rho = 1 + (s1 * 2.f > c2) + (s2 * 3.f > c3) + (s3 * 4.f > c4);
    float num = (rho == 1) ? c1 : (rho == 2) ? c2 : (rho == 3) ? c3 : c4;
    float theta = fmaxf(num / (float)rho, 0.f);
    theta = (ssum <= 1.f) ? 0.f : theta;
    o0 = copysignf(fmaxf(a0 - theta, 0.f), x0);
    o1 = copysignf(fmaxf(a1 - theta, 0.f), x1);
    o2 = copysignf(fmaxf(a2 - theta, 0.f), x2);
    o3 = copysignf(fmaxf(a3 - theta, 0.f), x3);
}

// ---------------- precompute kernel (float Jacobi, 12 sweeps) ----------------
__global__ void precomp_kernel(const float* __restrict__ sigma, const float* __restrict__ Qp,
                               const float* __restrict__ tausp, const float* __restrict__ lambp,
                               const float* __restrict__ epsp,
                               const float* __restrict__ w1, const float* __restrict__ b1,
                               const float* __restrict__ w2, const float* __restrict__ b2,
                               const float* __restrict__ w3, const float* __restrict__ b3) {
    __shared__ float h1[2][F_], h2[2][F_];
    int t = threadIdx.x;
    float lamb_e = expf(lambp[0]);
    float eps_e = expf(epsp[0]);
    if (t == 0) {
        g_pre.eps_e = eps_e;
        g_pre.inv_denom = 1.f / (1.f + lamb_e * (1.f + eps_e));
    }
    if (t < F_) {
        float Qm[4][4];
#pragma unroll
        for (int l = 0; l < 4; l++) {
            float rs = 0.f;
#pragma unroll
            for (int g = 0; g < 4; g++) rs += fabsf(Qp[t * 16 + l * 4 + g]);
            float inv = 1.f / fmaxf(rs, 1.f);
#pragma unroll
            for (int g = 0; g < 4; g++) Qm[l][g] = Qp[t * 16 + l * 4 + g] * inv;
        }
        float S[4][4];
        for (int i = 0; i < 4; i++)
            for (int j = 0; j < 4; j++) {
                float acc = 0.f;
                for (int l = 0; l < 4; l++) acc += Qm[l][i] * Qm[l][j];
                S[i][j] = acc;
            }
        const int JP[6] = {0, 0, 0, 1, 1, 2};
        const int JQ[6] = {1, 2, 3, 2, 3, 3};
        for (int sw = 0; sw < 12; sw++)
            for (int rr = 0; rr < 6; rr++) {
                int p = JP[rr], qq = JQ[rr];
                float apq = S[p][qq];
                if (fabsf(apq) < 1e-20f) continue;
                float th = (S[qq][qq] - S[p][p]) / (2.f * apq);
                float tt = (th >= 0.f ? 1.f : -1.f) / (fabsf(th) + sqrtf(1.f + th * th));
                float cc = rsqrtf(1.f + tt * tt), ss = tt * cc;
                for (int k = 0; k < 4; k++) {
                    float skp = S[k][p], skq = S[k][qq];
                    S[k][p] = cc * skp - ss * skq;
                    S[k][qq] = ss * skp + cc * skq;
                }
                for (int k = 0; k < 4; k++) {
                    float spk = S[p][k], sqk = S[qq][k];
                    S[p][k] = cc * spk - ss * sqk;
                    S[qq][k] = ss * spk + cc * sqk;
                }
            }
        float lam = S[0][0];
        for (int i = 1; i < 4; i++) lam = (S[i][i] > lam) ? S[i][i] : lam;
        float inv_lam = 1.f / lam;
#pragma unroll
        for (int l = 0; l < 4; l++)
#pragma unroll
            for (int g = 0; g < 4; g++) {
                g_pre.Qm[t][l][g] = Qm[l][g];
                g_pre.Qeff[t][l][g] = Qm[l][g] * inv_lam;
            }
        g_pre.its[t] = SCALE_C / expf(fmaxf(tausp[t], 0.f));
        for (int bb = 0; bb < 2; bb++)
            h1[bb][t] = fmaxf(fmaf(sigma[bb] * 20.f - 2.f, w1[t], b1[t]), 0.f);
    }
    __syncthreads();
    if (t < F_)
        for (int bb = 0; bb < 2; bb++) {
            float a = b2[t];
            for (int j = 0; j < F_; j++) a += h1[bb][j] * w2[j * F_ + t];
            h2[bb][t] = fmaxf(a, 0.f);
        }
    __syncthreads();
    if (t < F_)
        for (int bb = 0; bb < 2; bb++) {
            float a = b3[t];
            for (int j = 0; j < F_; j++) a += h2[bb][j] * w3[j * F_ + t];
            float sc = fmaxf(fmaf(a, 0.05f, sigma[bb]), 0.f) + 1e-9f;
            g_pre.invsc[bb][t] = 1.f / sc;
            g_pre.lscal[bb][t] = lamb_e * sc;
        }
}

// ---------------- HMMA main kernel: interleaved fwd/act/bwd per r6 quad ----------------
__global__ void __launch_bounds__(THREADS, 2)
mfoe_kernel(const float* __restrict__ xn, const float* __restrict__ Wf,
            const int* __restrict__ niter_p, float* __restrict__ out) {
    extern __shared__ char smc[];
    const uint32_t smb = smem_u32(smc);
    const int t = threadIdx.x;
    const int warp = t >> 5, lane = t & 31;
    const int r = lane >> 2, q = lane & 3;
    const int t8 = lane & 7, tb = lane >> 3;

    const int pix0 = blockIdx.x * 64;
    const int b = pix0 >> 14;
    const int sp0 = pix0 & 16383;
    const float* xnw = xn + (size_t)b * (C_ * 16384) + sp0 + warp * 16 + r;
    float* outw = out + (size_t)b * (C_ * 16384) + sp0 + warp * 16 + r;

    // ---- fill shared W tile (raw bf16) + Q tables + per-f scalars ----
    {
        __nv_bfloat16* wt = (__nv_bfloat16*)(smc + OFF_W);
        for (int i = t; i < GF * C_; i += THREADS) {
            int e = i >> 7, c = i & 127;
            wt[e * BFS + c] = __float2bfloat16(Wf[i]);
        }
        float* qes = (float*)(smc + OFF_QE);
        float* qms = (float*)(smc + OFF_QM);
        for (int i = t; i < 768; i += THREADS) {
            qes[i] = ((const float*)g_pre.Qeff)[i] * g_pre.its[i >> 4];
            qms[i] = ((const float*)g_pre.Qm)[i] * SCALE_C;
        }
        if (t < F_) {
            ((float*)(smc + OFF_ISC))[t] = g_pre.invsc[b][t];
            ((float*)(smc + OFF_LSC))[t] = g_pre.lscal[b][t];
        }
    }
    __syncthreads();

    const float eps_e = g_pre.eps_e;
    const float inv_denom = g_pre.inv_denom;
    const int niter = *niter_p;
    const float* qes = (const float*)(smc + OFF_QE);
    const float* qms = (const float*)(smc + OFF_QM);
    const float* ISC = (const float*)(smc + OFF_ISC);
    const float* LSC = (const float*)(smc + OFF_LSC);

    // ---- x state as packed bf16 hi/lo A-fragments ----
    uint32_t Ahs[8][4], Als[8][4];
#pragma unroll
    for (int n = 0; n < 16; n++) {
        int c0 = 8 * n + 2 * q;
        float x0 = xnw[(size_t)c0 * 16384];
        float x1 = xnw[(size_t)(c0 + 1) * 16384];
        float x2 = xnw[(size_t)c0 * 16384 + 8];
        float x3 = xnw[(size_t)(c0 + 1) * 16384 + 8];
        int m = n >> 1, base = (n & 1) * 2;
        Ahs[m][base] = packbf(x0, x1);
        float2 h0 = unpackbf(Ahs[m][base]);
        Als[m][base] = packbf(x0 - h0.x, x1 - h0.y);
        Ahs[m][base + 1] = packbf(x2, x3);
        float2 h1 = unpackbf(Ahs[m][base + 1]);
        Als[m][base + 1] = packbf(x2 - h1.x, x3 - h1.y);
    }

    for (int it = 0; it < niter; ++it) {
        // backward accumulators for all 16 c-tiles (live across the r6 loop)
        float acc[16][4];
#pragma unroll
        for (int n = 0; n < 16; n++) {
            acc[n][0] = 0.f; acc[n][1] = 0.f; acc[n][2] = 0.f; acc[n][3] = 0.f;
        }

        // ===== per r6 quad: forward (2-term) -> activation -> backward partial (1-term) =====
#pragma unroll
        for (int r6 = 0; r6 < 6; r6++) {
            float Df[4][4];
#pragma unroll
            for (int g = 0; g < 4; g++) { Df[g][0] = 0.f; Df[g][1] = 0.f; Df[g][2] = 0.f; Df[g][3] = 0.f; }
#pragma unroll
            for (int jp = 0; jp < 4; jp++) {
                uint32_t rowoff = smb + OFF_W + (uint32_t)(t8 * BFS + 32 * jp + 8 * tb) * 2;
#pragma unroll
                for (int g = 0; g < 4; g++) {
                    int n = r6 + 6 * g;
                    uint32_t bh[4];
                    ldsm4(bh, rowoff + (uint32_t)(8 * n * BFS) * 2);
                    mma16816(Df[g], Ahs[2 * jp], bh);
                    mma16816(Df[g], Als[2 * jp], bh);
                    mma16816(Df[g], Ahs[2 * jp + 1], bh + 2);
                    mma16816(Df[g], Als[2 * jp + 1], bh + 2);
                }
            }

            // activation on the quad -> vh4 (working, 8 regs x2)
            uint32_t vh4[4][2];
            {
                float vt[2][2][4];   // [h][fcol][g]
#pragma unroll
                for (int fcol = 0; fcol < 2; fcol++) {
                    int f = 8 * r6 + 2 * q + fcol;
                    float isc = ISC[f];
                    float ls  = LSC[f];
#pragma unroll
                    for (int h = 0; h < 2; h++) {
                        int di = 2 * h + fcol;
                        float xv0 = Df[0][di] * isc, xv1 = Df[1][di] * isc;
                        float xv2 = Df[2][di] * isc, xv3 = Df[3][di] * isc;

                        float gc0, gc1, gc2, gc3;
                        proj4(xv0, xv1, xv2, xv3, gc0, gc1, gc2, gc3);
                        gc0 = fmaf(eps_e, xv0, gc0);
                        gc1 = fmaf(eps_e, xv1, gc1);
                        gc2 = fmaf(eps_e, xv2, gc2);
                        gc3 = fmaf(eps_e, xv3, gc3);

                        float y[4];
#pragma unroll
                        for (int l = 0; l < 4; l++) {
                            float4 qe = *(const float4*)(qes + f * 16 + 4 * l);
                            y[l] = qe.x * xv0 + qe.y * xv1 + qe.z * xv2 + qe.w * xv3;
                        }

                        float gy[4];
                        proj4(y[0], y[1], y[2], y[3], gy[0], gy[1], gy[2], gy[3]);
#pragma unroll
                        for (int l = 0; l < 4; l++) gy[l] = fmaf(eps_e, y[l], gy[l]);

                        float v0 = gc0, v1 = gc1, v2 = gc2, v3 = gc3;
#pragma unroll
                        for (int l = 0; l < 4; l++) {
                            float4 qm = *(const float4*)(qms + f * 16 + 4 * l);
                            v0 -= qm.x * gy[l];
                            v1 -= qm.y * gy[l];
                            v2 -= qm.z * gy[l];
                            v3 -= qm.w * gy[l];
                        }
                        vt[h][fcol][0] = ls * v0;
                        vt[h][fcol][1] = ls * v1;
                        vt[h][fcol][2] = ls * v2;
                        vt[h][fcol][3] = ls * v3;
                    }
                }
#pragma unroll
                for (int g = 0; g < 4; g++) {
                    vh4[g][0] = packbf(vt[0][0][g], vt[0][1][g]);
                    vh4[g][1] = packbf(vt[1][0][g], vt[1][1][g]);
                }
            }

            // backward partial: chunkA = e-tiles (r6, r6+6), chunkB = (r6+12, r6+18)
            {
                uint32_t AA[4] = {vh4[0][0], vh4[0][1], vh4[1][0], vh4[1][1]};
                uint32_t AB[4] = {vh4[2][0], vh4[2][1], vh4[3][0], vh4[3][1]};
                // per-lane ldsm row: e = 8*(r6 + 6*(tb&1)) + t8  (chunkA), +96 for chunkB
                uint32_t ebaseA = (uint32_t)(8 * r6 + 48 * (tb & 1) + t8);
#pragma unroll
                for (int p = 0; p < 8; p++) {
                    uint32_t col = (uint32_t)(16 * p + 8 * (tb >> 1));
                    uint32_t btA[4], btB[4];
                    ldsm4t(btA, smb + OFF_W + (ebaseA * BFS + col) * 2);
                    ldsm4t(btB, smb + OFF_W + ((ebaseA + 96) * BFS + col) * 2);
                    mma16816(acc[2 * p], AA, btA);
                    mma16816(acc[2 * p + 1], AA, btA + 2);
                    mma16816(acc[2 * p], AB, btB);
                    mma16816(acc[2 * p + 1], AB, btB + 2);
                }
            }
        }

        // ===== x update from accumulated D_b =====
#pragma unroll
        for (int n = 0; n < 16; n++) {
            int c0 = 8 * n + 2 * q;
            float n0 = xnw[(size_t)c0 * 16384];
            float n1 = xnw[(size_t)(c0 + 1) * 16384];
            float n2 = xnw[(size_t)c0 * 16384 + 8];
            float n3 = xnw[(size_t)(c0 + 1) * 16384 + 8];
            int m = n >> 1, base = (n & 1) * 2;
            float2 h0 = unpackbf(Ahs[m][base]);
            float2 h1 = unpackbf(Ahs[m][base + 1]);
            float2 l0 = unpackbf(Als[m][base]);
            float2 l1 = unpackbf(Als[m][base + 1]);
            float x0 = h0.x + l0.x, x1 = h0.y + l0.y;
            float x2 = h1.x + l1.x, x3 = h1.y + l1.y;
            x0 -= (x0 - n0 + acc[n][0]) * inv_denom;
            x1 -= (x1 - n1 + acc[n][1]) * inv_denom;
            x2 -= (x2 - n2 + acc[n][2]) * inv_denom;
            x3 -= (x3 - n3 + acc[n][3]) * inv_denom;
            Ahs[m][base] = packbf(x0, x1);
            float2 nh0 = unpackbf(Ahs[m][base]);
            Als[m][base] = packbf(x0 - nh0.x, x1 - nh0.y);
            Ahs[m][base + 1] = packbf(x2, x3);
            float2 nh1 = unpackbf(Ahs[m][base + 1]);
            Als[m][base + 1] = packbf(x2 - nh1.x, x3 - nh1.y);
        }
    }

    // ---- output: reconstruct and store ----
#pragma unroll
    for (int n = 0; n < 16; n++) {
        int c0 = 8 * n + 2 * q;
        int m = n >> 1, base = (n & 1) * 2;
        float2 h0 = unpackbf(Ahs[m][base]);
        float2 h1 = unpackbf(Ahs[m][base + 1]);
        float2 l0 = unpackbf(Als[m][base]);
        float2 l1 = unpackbf(Als[m][base + 1]);
        outw[(size_t)c0 * 16384] = h0.x + l0.x;
        outw[(size_t)(c0 + 1) * 16384] = h0.y + l0.y;
        outw[(size_t)c0 * 16384 + 8] = h1.x + l1.x;
        outw[(size_t)(c0 + 1) * 16384 + 8] = h1.y + l1.y;
    }
}

extern "C" void kernel_launch(void* const* d_in, const int* in_sizes, int n_in,
                              void* d_out, int out_size) {
    const float* xn    = (const float*)d_in[0];
    const float* sigma = (const float*)d_in[1];
    const float* Qp    = (const float*)d_in[2];
    const float* tausp = (const float*)d_in[3];
    const float* lamb  = (const float*)d_in[4];
    const float* epso  = (const float*)d_in[5];
    const float* w1    = (const float*)d_in[6];
    const float* b1    = (const float*)d_in[7];
    const float* w2    = (const float*)d_in[8];
    const float* b2    = (const float*)d_in[9];
    const float* w3    = (const float*)d_in[10];
    const float* b3    = (const float*)d_in[11];
    const float* Wf    = (const float*)d_in[12];
    const int* niter   = (const int*)d_in[13];
    float* out = (float*)d_out;

    cudaFuncSetAttribute(mfoe_kernel, cudaFuncAttributeMaxDynamicSharedMemorySize, SMEM_BYTES);
    precomp_kernel<<<1, 64>>>(sigma, Qp, tausp, lamb, epso, w1, b1, w2, b2, w3, b3);
    mfoe_kernel<<<512, THREADS, SMEM_BYTES>>>(xn, Wf, niter, out);
}